// round 7
// baseline (speedup 1.0000x reference)
#include <cuda_runtime.h>
#include <math.h>

// Problem constants
#define BB   16
#define CC   768          // channels == sequence length L
#define LL   768
#define DM   64           // d_model
#define DI   128          // d_inner
#define DS   16           // d_state
#define NROW (BB*CC)      // 12288 rows per image / per branch

#define NCH  6            // scan chunks
#define CHL  128          // chunk length
#define STG  64           // smem staging length (2 subs per chunk)

// ---------------- scratch (device globals; allocation-free rule) ------------
__device__ float  g_x[2u*NROW*DM];       // LN'd pre-projected features (2 imgs)
__device__ float  g_xz[2u*NROW*256];     // in_proj outputs, (img, b*L+l, 256)
__device__ float2 g_dtx[3u*NROW*DI];     // (softplus dt, silu(conv x)) per branch, scan order
__device__ float  g_bc[3u*NROW*32];      // B/C permuted: row*32 + q*8 + k:
                                         //   k<4 -> B[q+4k], k>=4 -> C[q+4(k-4)]
__device__ float  g_v[DI];               // out_proj_w^T @ post_w  (collapsed epilogue)
__device__ float  g_part[(size_t)NROW*12]; // per (b,l): 12 partials (3 br x 4 dg)
// chunked-scan intermediates: bb = br*16+b (48), chunks 0..4, 2048 (d,s) states
__device__ float  g_P[48u*5*2048];       // per-chunk state decay products
__device__ float  g_q[48u*5*2048];       // per-chunk local end states

struct BP { const float *cw, *cb, *xp, *dtw, *dtb, *Alog, *Dp; };
struct AP { BP br[3]; };

// ============================================================================
// Kernel 0: v = out_proj_w^T @ post_w (tiny; also keeps the ncu -s window on
// k_conv_proj as the captured 4th launch).
// ============================================================================
__global__ __launch_bounds__(128) void k_prev(
    const float* __restrict__ opw, const float* __restrict__ pw)
{
    int t = threadIdx.x;
    float acc = 0.0f;
    #pragma unroll 8
    for (int m = 0; m < 64; m++) acc = fmaf(__ldg(pw + m), __ldg(opw + m*128 + t), acc);
    g_v[t] = acc;
}

// ============================================================================
// Kernel 1: block-mean pool 32x32 -> 4x4, pre-proj 16->64, LayerNorm(64)
// ============================================================================
__global__ __launch_bounds__(128) void k_pool_pre_ln(
    const float* __restrict__ img1, const float* __restrict__ img2,
    const float* __restrict__ pre_w, const float* __restrict__ pre_b,
    const float* __restrict__ ln_g,  const float* __restrict__ ln_b)
{
    int bid = blockIdx.x;
    int img = (bid >= NROW) ? 1 : 0;
    int rc  = bid - img*NROW;                 // b*768 + c
    const float* src = (img ? img2 : img1) + (size_t)rc * 1024;

    __shared__ float pool[16];
    __shared__ float red[4];

    int t = threadIdx.x;
    int cell = t >> 3;           // 0..15
    int k    = t & 7;
    int pi = cell >> 2, pj = cell & 3;
    int row = pi*8 + k;
    const float4* p4 = (const float4*)(src + row*32 + pj*8);
    float4 a = p4[0], b4 = p4[1];
    float s = a.x+a.y+a.z+a.w + b4.x+b4.y+b4.z+b4.w;
    s += __shfl_xor_sync(0xffffffffu, s, 4);
    s += __shfl_xor_sync(0xffffffffu, s, 2);
    s += __shfl_xor_sync(0xffffffffu, s, 1);
    if (k == 0) pool[cell] = s * (1.0f/64.0f);
    __syncthreads();

    float y = 0.0f;
    if (t < DM) {
        y = __ldg(pre_b + t);
        #pragma unroll
        for (int q = 0; q < 16; q++) y = fmaf(__ldg(pre_w + t*16 + q), pool[q], y);
    }
    float sum = (t < DM) ? y : 0.0f;
    float sq  = (t < DM) ? y*y : 0.0f;
    #pragma unroll
    for (int m = 16; m >= 1; m >>= 1) {
        sum += __shfl_xor_sync(0xffffffffu, sum, m);
        sq  += __shfl_xor_sync(0xffffffffu, sq,  m);
    }
    if (t < DM && (t & 31) == 0) { red[t>>5] = sum; red[2+(t>>5)] = sq; }
    __syncthreads();
    if (t < DM) {
        float mu  = (red[0]+red[1]) * (1.0f/64.0f);
        float var = (red[2]+red[3]) * (1.0f/64.0f) - mu*mu;
        float o = (y - mu) * rsqrtf(var + 1e-5f) * __ldg(ln_g + t) + __ldg(ln_b + t);
        g_x[((size_t)img*NROW + rc)*DM + t] = o;
    }
}

// ============================================================================
// Kernel 2: in_proj  (B*L, 64) @ (256,64)^T -> (B*L, 256), per image.
// ============================================================================
__global__ __launch_bounds__(256) void k_inproj(
    const float* __restrict__ w0, const float* __restrict__ w1)
{
    int img = blockIdx.y;
    const float* W = img ? w1 : w0;
    int r0 = blockIdx.x * 24;
    int t  = threadIdx.x;

    float w[64];
    const float4* W4 = (const float4*)(W + t*64);
    #pragma unroll
    for (int q = 0; q < 16; q++) {
        float4 v = W4[q];
        w[4*q+0]=v.x; w[4*q+1]=v.y; w[4*q+2]=v.z; w[4*q+3]=v.w;
    }

    __shared__ __align__(16) float xs[8*64];
    const float* xin   = g_x  + (size_t)img*NROW*DM;
    float*       xzout = g_xz + (size_t)img*NROW*256;

    for (int sub = 0; sub < 3; sub++) {
        int rbase = r0 + sub*8;
        __syncthreads();
        for (int i = t; i < 512; i += 256) xs[i] = xin[(size_t)rbase*DM + i];
        __syncthreads();
        #pragma unroll
        for (int r = 0; r < 8; r++) {
            const float4* x4 = (const float4*)(xs + r*64);
            float acc = 0.0f;
            #pragma unroll
            for (int q = 0; q < 16; q++) {
                float4 v = x4[q];
                acc = fmaf(v.x, w[4*q+0], acc);
                acc = fmaf(v.y, w[4*q+1], acc);
                acc = fmaf(v.z, w[4*q+2], acc);
                acc = fmaf(v.w, w[4*q+3], acc);
            }
            xzout[(size_t)(rbase+r)*256 + t] = acc;
        }
    }
}

// ============================================================================
// Kernel 3: causal depthwise conv(K=4)+silu, x-proj (128->36), dt-proj+softplus.
// 576 blocks x 2 row-tiles (weights staged once per block). Tail-free GEMM:
//   B/C (32x32) = 256 2x2 register tiles = exactly 256 threads, 1 pass;
//   dt cols (32x4) = split-k, 2 threads/output + shfl, 1/4 pass.
// ============================================================================
__global__ __launch_bounds__(256) void k_conv_proj(AP P)
{
    int br = blockIdx.z, b = blockIdx.y;
    const BP Bp = P.br[br];

    __shared__ __align__(16) float xs[35*128];   // input rows; rows 3..34 reused for conv out
    __shared__ __align__(16) float xp_s[128*36]; // xproj transposed: xp_s[k*36+j]
    __shared__ float dbc_s[32*36];
    __shared__ float cw_s[512];                  // conv w, k-major
    __shared__ float dtw_s[512];                 // dt w, r-major
    __shared__ float cb_s[128], dtb_s[128];

    int t = threadIdx.x;
    for (int i = t; i < 128*36; i += 256) {
        int j = i >> 7, k = i & 127;
        xp_s[k*36 + j] = __ldg(Bp.xp + i);       // xproj_w[j*128+k]
    }
    for (int i = t; i < 512; i += 256) {
        cw_s [(i&3)*128 + (i>>2)] = __ldg(Bp.cw + i);
        dtw_s[(i&3)*128 + (i>>2)] = __ldg(Bp.dtw + i);
    }
    if (t < 128) { cb_s[t] = __ldg(Bp.cb + t); dtb_s[t] = __ldg(Bp.dtb + t); }

    const float* xzsrc = g_xz + ((br == 2) ? (size_t)NROW*256 : 0);

    for (int tile = 0; tile < 2; tile++) {
        int p0 = (blockIdx.x*2 + tile) * 32;
        __syncthreads();                         // weights ready / prev tile done
        // stage source rows p0-3 .. p0+31
        for (int i = t; i < 35*128; i += 256) {
            int r = i >> 7, d = i & 127;
            int p = p0 - 3 + r;                  // scan index
            float v = 0.0f;
            if (p >= 0) {
                int l = (br == 1) ? (767 - p) : p;
                v = xzsrc[(size_t)(b*LL + l)*256 + d];
            }
            xs[i] = v;
        }
        __syncthreads();

        // causal depthwise conv + silu (const-trip -> xc stays in regs)
        float xc[16];
        #pragma unroll
        for (int it = 0; it < 16; it++) {
            int i = t + it*256;
            int p = i >> 7, d = i & 127;
            float acc = cb_s[d];
            #pragma unroll
            for (int kk = 0; kk < 4; kk++)
                acc = fmaf(cw_s[kk*128 + d], xs[(p+kk)*128 + d], acc);
            float sg = 1.0f / (1.0f + __expf(-acc));
            xc[it] = acc * sg;
        }
        __syncthreads();
        #pragma unroll
        for (int it = 0; it < 16; it++) {
            int i = t + it*256;
            int p = i >> 7, d = i & 127;
            xs[(p+3)*128 + d] = xc[it];          // conv-output tile in place
        }
        __syncthreads();

        // ---- B/C GEMM: 32 rows x 32 cols (j=4..35), 2x2 tiles, 256 threads, no tail
        {
            int pg = t >> 4, jg = t & 15;
            int p = 2*pg, j = 4 + 2*jg;
            float a00=0.f, a01=0.f, a10=0.f, a11=0.f;
            const float* xr0 = xs + (p+3)*128;
            const float* xr1 = xs + (p+4)*128;
            const float* wc  = xp_s + j;
            #pragma unroll 4
            for (int k = 0; k < 128; k += 2) {
                float2 x0 = *(const float2*)&xr0[k];
                float2 x1 = *(const float2*)&xr1[k];
                float2 u0 = *(const float2*)&wc[k*36];
                float2 u1 = *(const float2*)&wc[(k+1)*36];
                a00 = fmaf(x0.x, u0.x, a00); a01 = fmaf(x0.x, u0.y, a01);
                a10 = fmaf(x1.x, u0.x, a10); a11 = fmaf(x1.x, u0.y, a11);
                a00 = fmaf(x0.y, u1.x, a00); a01 = fmaf(x0.y, u1.y, a01);
                a10 = fmaf(x1.y, u1.x, a10); a11 = fmaf(x1.y, u1.y, a11);
            }
            dbc_s[p*36 + j]       = a00;
            dbc_s[p*36 + j + 1]   = a01;
            dbc_s[(p+1)*36 + j]   = a10;
            dbc_s[(p+1)*36 + j+1] = a11;
        }
        // ---- dt columns (j=0..3): 128 outputs, 2 threads each (split-k 64+64)
        {
            int oi = t >> 1, half = t & 1;
            int p = oi >> 2, j = oi & 3;
            const float* xr = xs + (p+3)*128 + half*64;
            const float* wc = xp_s + (half*64)*36 + j;
            float acc = 0.0f;
            #pragma unroll 8
            for (int k = 0; k < 64; k += 2) {
                float2 x = *(const float2*)&xr[k];
                acc = fmaf(x.x, wc[k*36],     acc);
                acc = fmaf(x.y, wc[(k+1)*36], acc);
            }
            acc += __shfl_xor_sync(0xffffffffu, acc, 1);
            if (half == 0) dbc_s[p*36 + j] = acc;
        }
        __syncthreads();

        // dt = softplus(dbc[:4] @ dtw^T + dtb); write fused (dt, xconv) float2
        size_t obase = (size_t)((br*BB + b)*LL + p0) * DI;
        #pragma unroll
        for (int it = 0; it < 16; it++) {
            int i = t + it*256;
            int p = i >> 7, d = i & 127;
            float acc = dtb_s[d];
            #pragma unroll
            for (int r = 0; r < 4; r++)
                acc = fmaf(dtw_s[r*128 + d], dbc_s[p*36 + r], acc);
            float sp = (acc > 20.0f) ? acc : log1pf(__expf(acc));
            g_dtx[obase + i] = make_float2(sp, xs[(p+3)*128 + d]);
        }
        // B/C permuted: row*32 + q*8 + k ; k<4 -> B[q+4k], k>=4 -> C[q+4(k-4)]
        size_t sbase = (size_t)((br*BB + b)*LL + p0) * 32;
        for (int i = t; i < 1024; i += 256) {
            int p = i >> 5, c = i & 31;
            int q = c >> 3, k = c & 7;
            float v = (k < 4) ? dbc_s[p*36 + 4  + q + 4*k]
                              : dbc_s[p*36 + 20 + q + 4*(k-4)];
            g_bc[sbase + i] = v;
        }
    }
}

// ============================================================================
// Kernel 4a: scan pass 1 — per-chunk (P = prod dA, q = local end state),
// chunks 0..4. grid (4 dg * 5 ch, 16, 3) = 960 blocks, 128 thr = 32 d x 4 q.
// ============================================================================
__global__ __launch_bounds__(128) void k_scan1(AP P)
{
    int bx = blockIdx.x;
    int dg = bx / 5, ch = bx - dg*5;
    int b = blockIdx.y, br = blockIdx.z;
    int d0 = dg * 32;
    int t  = threadIdx.x;
    int dl = t >> 2, q = t & 3;
    int d  = d0 + dl;
    const BP Bp = P.br[br];

    float A[4], h[4] = {0,0,0,0}, Pp[4] = {1,1,1,1};
    #pragma unroll
    for (int k = 0; k < 4; k++) A[k] = -expf(__ldg(Bp.Alog + d*DS + q + 4*k));

    __shared__ __align__(16) float2 sdtx[STG*32];
    __shared__ __align__(16) float  sb[STG*16];

    int bb = br*BB + b;
    size_t rbase = (size_t)bb * LL;

    for (int sub = 0; sub < 2; sub++) {
        int q0 = ch*CHL + sub*STG;
        __syncthreads();
        for (int i = t; i < STG*32; i += 128) {
            int tt = i >> 5, dd = i & 31;
            sdtx[i] = g_dtx[(rbase + q0 + tt)*DI + d0 + dd];
        }
        for (int i = t; i < STG*16; i += 128) {
            int tt = i >> 4, c = i & 15;
            sb[i] = g_bc[(rbase + q0 + tt)*32 + (c>>2)*8 + (c&3)];
        }
        __syncthreads();

        for (int tb = 0; tb < STG; tb += 4) {
            float2 dx[4]; float4 bq[4];
            #pragma unroll
            for (int j = 0; j < 4; j++) {
                dx[j] = sdtx[(tb+j)*32 + dl];
                bq[j] = *(const float4*)&sb[((tb+j)*4 + q)*4];
            }
            float e[4][4];
            #pragma unroll
            for (int j = 0; j < 4; j++) {
                e[j][0] = __expf(dx[j].x*A[0]);
                e[j][1] = __expf(dx[j].x*A[1]);
                e[j][2] = __expf(dx[j].x*A[2]);
                e[j][3] = __expf(dx[j].x*A[3]);
            }
            #pragma unroll
            for (int j = 0; j < 4; j++) {
                float u = dx[j].x * dx[j].y;
                h[0] = fmaf(e[j][0], h[0], bq[j].x * u);
                h[1] = fmaf(e[j][1], h[1], bq[j].y * u);
                h[2] = fmaf(e[j][2], h[2], bq[j].z * u);
                h[3] = fmaf(e[j][3], h[3], bq[j].w * u);
            }
            #pragma unroll
            for (int k = 0; k < 4; k++)
                Pp[k] *= (e[0][k]*e[1][k])*(e[2][k]*e[3][k]);
        }
    }
    size_t pidx = ((size_t)(bb*5 + ch))*2048 + (size_t)d*16 + q;
    #pragma unroll
    for (int k = 0; k < 4; k++) {
        g_P[pidx + 4*k] = Pp[k];
        g_q[pidx + 4*k] = h[k];
    }
}

// ============================================================================
// Kernel 4b: scan pass 2 — inline boundary combine; outputs per-(row,dg)
// partial dot products against v (epilogue collapsed).
// grid (4 dg * 6 ch, 16, 3) = 1152 blocks, 128 thr = 32 d x 4 q.
// ============================================================================
__global__ __launch_bounds__(128) void k_scan2(AP P)
{
    int bx = blockIdx.x;
    int dg = bx / 6, ch = bx - dg*6;
    int b = blockIdx.y, br = blockIdx.z;
    int d0 = dg * 32;
    int t  = threadIdx.x;
    int dl = t >> 2, q = t & 3;
    int d  = d0 + dl;
    const BP Bp = P.br[br];

    float A[4];
    #pragma unroll
    for (int k = 0; k < 4; k++) A[k] = -expf(__ldg(Bp.Alog + d*DS + q + 4*k));
    float Dp = __ldg(Bp.Dp + d);

    int bb = br*BB + b;
    float h[4] = {0,0,0,0};
    for (int c = 0; c < ch; c++) {                 // inline boundary combine
        size_t s = ((size_t)(bb*5 + c))*2048 + (size_t)d*16 + q;
        #pragma unroll
        for (int k = 0; k < 4; k++)
            h[k] = fmaf(g_P[s + 4*k], h[k], g_q[s + 4*k]);
    }

    __shared__ __align__(16) float2 sdtx[STG*32];
    __shared__ __align__(16) float  sbc[STG*32];
    __shared__ float sy[STG*32];
    __shared__ float v_s[32];

    if (t < 32) v_s[t] = g_v[d0 + t];

    size_t rbase = (size_t)bb * LL;
    const float* zsrc = g_xz + ((br == 2) ? (size_t)NROW*256 : 0)
                             + (size_t)b*LL*256 + 128 + d0;
    const int rev  = (br == 1);
    const int lb   = rev ? 767 : 0;
    const int lsgn = rev ? -1 : 1;

    for (int sub = 0; sub < 2; sub++) {
        int q0 = ch*CHL + sub*STG;
        __syncthreads();
        for (int i = t; i < STG*32; i += 128) {
            int tt = i >> 5, dd = i & 31;
            sdtx[i] = g_dtx[(rbase + q0 + tt)*DI + d0 + dd];
            sbc[i]  = g_bc [(rbase + q0 + tt)*32 + dd];
        }
        __syncthreads();

        for (int tb = 0; tb < STG; tb += 4) {
            float2 dx[4]; float4 bq[4], cq[4]; float py[4];
            #pragma unroll
            for (int j = 0; j < 4; j++) {
                dx[j] = sdtx[(tb+j)*32 + dl];
                bq[j] = *(const float4*)&sbc[(tb+j)*32 + q*8];
                cq[j] = *(const float4*)&sbc[(tb+j)*32 + q*8 + 4];
            }
            float e[4][4];
            #pragma unroll
            for (int j = 0; j < 4; j++) {
                e[j][0] = __expf(dx[j].x*A[0]);
                e[j][1] = __expf(dx[j].x*A[1]);
                e[j][2] = __expf(dx[j].x*A[2]);
                e[j][3] = __expf(dx[j].x*A[3]);
            }
            #pragma unroll
            for (int j = 0; j < 4; j++) {
                float u = dx[j].x * dx[j].y;
                h[0] = fmaf(e[j][0], h[0], bq[j].x * u);
                h[1] = fmaf(e[j][1], h[1], bq[j].y * u);
                h[2] = fmaf(e[j][2], h[2], bq[j].z * u);
                h[3] = fmaf(e[j][3], h[3], bq[j].w * u);
                float p = h[0]*cq[j].x;
                p = fmaf(h[1], cq[j].y, p);
                p = fmaf(h[2], cq[j].z, p);
                py[j] = fmaf(h[3], cq[j].w, p);
            }
            #pragma unroll
            for (int j = 0; j < 4; j++) {
                py[j] += __shfl_xor_sync(0xffffffffu, py[j], 2);
                py[j] += __shfl_xor_sync(0xffffffffu, py[j], 1);
            }
            if (q == 0) {
                #pragma unroll
                for (int j = 0; j < 4; j++)
                    sy[(tb+j)*32 + dl] = fmaf(dx[j].y, Dp, py[j]);
            }
        }
        __syncthreads();

        // gated partial dot with v: 2 threads per row, 16 d's each
        {
            int row  = t >> 1, half = t & 1;
            int qq   = q0 + row;
            int l    = lb + lsgn*qq;
            const float* zr = zsrc + (size_t)l*256 + half*16;
            const float* yr = sy + row*32 + half*16;
            const float* vr = v_s + half*16;
            float acc = 0.0f;
            #pragma unroll
            for (int dd = 0; dd < 16; dd++) {
                float zv = zr[dd];
                float sg = zv / (1.0f + __expf(-zv));
                acc = fmaf(yr[dd]*sg, vr[dd], acc);
            }
            acc += __shfl_xor_sync(0xffffffffu, acc, 1);
            if (half == 0)
                g_part[((size_t)(b*LL + l))*12 + br*4 + dg] = acc;
        }
    }
}

// ============================================================================
// Kernel 5: att = sigmoid((sum of 12 partials + post_b)/2) + 1e-6
// ============================================================================
__global__ __launch_bounds__(256) void k_final(
    const float* __restrict__ pb, float* __restrict__ out)
{
    int row = blockIdx.x*256 + threadIdx.x;
    const float4* p = (const float4*)(g_part + (size_t)row*12);
    float4 a = p[0], b4 = p[1], c = p[2];
    float s = (a.x+a.y)+(a.z+a.w) + (b4.x+b4.y)+(b4.z+b4.w) + (c.x+c.y)+(c.z+c.w);
    float o = (s + __ldg(pb)) * 0.5f;
    out[row] = 1.0f / (1.0f + __expf(-o)) + 1e-6f;
}

// ============================================================================
extern "C" void kernel_launch(void* const* d_in, const int* in_sizes, int n_in,
                              void* d_out, int out_size)
{
    const float* img1 = (const float*)d_in[0];
    const float* img2 = (const float*)d_in[1];
    const float* pre_w = (const float*)d_in[2];
    const float* pre_b = (const float*)d_in[3];
    const float* ln_g  = (const float*)d_in[4];
    const float* ln_b  = (const float*)d_in[5];
    const float* in_proj_w   = (const float*)d_in[6];
    const float* in_proj_s_w = (const float*)d_in[7];
    const float* out_proj_w  = (const float*)d_in[8];
    const float* post_w = (const float*)d_in[9];
    const float* post_b = (const float*)d_in[10];

    AP P;
    for (int t = 0; t < 3; t++) {
        int o = 11 + 7*t;              // f, b, s
        P.br[t].cw   = (const float*)d_in[o+0];
        P.br[t].cb   = (const float*)d_in[o+1];
        P.br[t].xp   = (const float*)d_in[o+2];
        P.br[t].dtw  = (const float*)d_in[o+3];
        P.br[t].dtb  = (const float*)d_in[o+4];
        P.br[t].Alog = (const float*)d_in[o+5];
        P.br[t].Dp   = (const float*)d_in[o+6];
    }

    k_prev<<<1, 128>>>(out_proj_w, post_w);
    k_pool_pre_ln<<<2*NROW, 128>>>(img1, img2, pre_w, pre_b, ln_g, ln_b);
    k_inproj<<<dim3(512, 2), 256>>>(in_proj_w, in_proj_s_w);
    k_conv_proj<<<dim3(12, 16, 3), 256>>>(P);
    k_scan1<<<dim3(20, 16, 3), 128>>>(P);
    k_scan2<<<dim3(24, 16, 3), 128>>>(P);
    k_final<<<48, 256>>>(post_b, (float*)d_out);
    (void)in_sizes; (void)n_in; (void)out_size;
}

// round 8
// speedup vs baseline: 1.1984x; 1.1984x over previous
#include <cuda_runtime.h>
#include <math.h>

// Problem constants
#define BB   16
#define CC   768          // channels == sequence length L
#define LL   768
#define DM   64           // d_model
#define DI   128          // d_inner
#define DS   16           // d_state
#define NROW (BB*CC)      // 12288 rows per image / per branch

#define NCH  6            // scan chunks
#define CHL  128          // chunk length
#define STG  64           // smem staging length (2 subs per chunk)

// ---------------- scratch (device globals; allocation-free rule) ------------
__device__ float  g_xz[2u*NROW*256];     // in_proj outputs, (img, b*L+l, 256)
__device__ float2 g_dtx[3u*NROW*DI];     // (softplus dt, silu(conv x)) per branch, scan order
__device__ float  g_bc[3u*NROW*32];      // B/C permuted: row*32 + q*8 + k:
                                         //   k<4 -> B[q+4k], k>=4 -> C[q+4(k-4)]
__device__ float  g_v[DI];               // out_proj_w^T @ post_w  (collapsed epilogue)
__device__ float  g_part[(size_t)NROW*12]; // per (b,l): 12 partials (3 br x 4 dg)
// chunked-scan intermediates
__device__ float  g_P[48u*5*2048];       // per-chunk state decay products
__device__ float  g_q[48u*5*2048];       // per-chunk local end states
// prepped weights (linear, load-friendly layouts)
__device__ float  g_wxp[3u*4608];        // xproj transposed: [br][k*36+j]
__device__ float  g_wcv[3u*512];         // conv w k-major:   [br][kk*128+d]
__device__ float  g_wdt[3u*512];         // dt w r-major:     [br][r*128+d]
__device__ float  g_A  [3u*2048];        // -exp(A_log):      [br][d*16+s]

struct BP { const float *cw, *cb, *xp, *dtw, *dtb, *Alog, *Dp; };
struct AP { BP br[3]; };

// ============================================================================
// Prep kernels (tiny; also place k_front at ncu's captured 4th launch)
// ============================================================================
__global__ __launch_bounds__(256) void k_prep_w(AP P)
{
    int br = blockIdx.x, t = threadIdx.x;
    const BP Bp = P.br[br];
    float* wxp = g_wxp + br*4608;
    for (int i = t; i < 4608; i += 256) {
        int k = i / 36, j = i - k*36;
        wxp[i] = __ldg(Bp.xp + j*128 + k);         // xproj_w[j][k]
    }
    float* wcv = g_wcv + br*512;
    float* wdt = g_wdt + br*512;
    for (int i = t; i < 512; i += 256) {
        int kk = i >> 7, d = i & 127;
        wcv[i] = __ldg(Bp.cw  + d*4 + kk);
        wdt[i] = __ldg(Bp.dtw + d*4 + kk);
    }
}

__global__ __launch_bounds__(256) void k_prep_A(AP P)
{
    int br = blockIdx.x, t = threadIdx.x;
    const float* al = P.br[br].Alog;
    for (int i = t; i < 2048; i += 256) g_A[br*2048 + i] = -expf(__ldg(al + i));
}

__global__ __launch_bounds__(128) void k_prep_v(
    const float* __restrict__ opw, const float* __restrict__ pw)
{
    int t = threadIdx.x;
    float acc = 0.0f;
    #pragma unroll 8
    for (int m = 0; m < 64; m++) acc = fmaf(__ldg(pw + m), __ldg(opw + m*128 + t), acc);
    g_v[t] = acc;
}

// ============================================================================
// Kernel 1 (fused front): pool 32x32->4x4, pre-proj 16->64, LayerNorm, in_proj
// 64->256. grid (48 c-chunks, 16 b, 2 img), 256 threads. Replaces pool+inproj
// and the g_x round-trip.
// ============================================================================
__global__ __launch_bounds__(256) void k_front(
    const float* __restrict__ img1, const float* __restrict__ img2,
    const float* __restrict__ pre_w, const float* __restrict__ pre_b,
    const float* __restrict__ ln_g,  const float* __restrict__ ln_b,
    const float* __restrict__ w0,    const float* __restrict__ w1)
{
    int img = blockIdx.z, b = blockIdx.y, c0 = blockIdx.x * 16;
    const float* src = (img ? img2 : img1) + ((size_t)(b*CC + c0)) * 1024;

    __shared__ float pw_s[16*64];        // transposed: pw_s[q*64+m]
    __shared__ float pb_s[64], lg_s[64], lb_s[64];
    __shared__ float pool_s[16*16];
    __shared__ __align__(16) float xrow[16*64];

    int t = threadIdx.x;
    // stage pre weights (dst-major: coalesced smem writes, scattered L1 reads)
    for (int i = t; i < 1024; i += 256) {
        int q = i >> 6, m = i & 63;
        pw_s[i] = __ldg(pre_w + m*16 + q);
    }
    if (t < 64) { pb_s[t] = __ldg(pre_b+t); lg_s[t] = __ldg(ln_g+t); lb_s[t] = __ldg(ln_b+t); }

    // phase 1: pool. thread owns (row r=t>>4, cell=t&15); cell = pi*4+pj
    {
        int r = t >> 4, cell = t & 15;
        int pi = cell >> 2, pj = cell & 3;
        const float* rp = src + (size_t)r*1024 + pi*8*32 + pj*8;
        float s = 0.0f;
        #pragma unroll
        for (int sr = 0; sr < 8; sr++) {
            float4 a = *(const float4*)(rp + sr*32);
            float4 c = *(const float4*)(rp + sr*32 + 4);
            s += ((a.x+a.y)+(a.z+a.w)) + ((c.x+c.y)+(c.z+c.w));
        }
        pool_s[r*16 + cell] = s * (1.0f/64.0f);
    }
    __syncthreads();

    // phase 2: pre-proj + LN. 16 threads/row, thread g owns m = g+16k (k=0..3)
    {
        int r = t >> 4, g = t & 15;
        float y[4], sum = 0.0f, sq = 0.0f;
        #pragma unroll
        for (int k = 0; k < 4; k++) {
            int m = g + 16*k;
            float acc = pb_s[m];
            #pragma unroll
            for (int q = 0; q < 16; q++)
                acc = fmaf(pw_s[q*64 + m], pool_s[r*16 + q], acc);
            y[k] = acc; sum += acc; sq = fmaf(acc, acc, sq);
        }
        #pragma unroll
        for (int m = 8; m >= 1; m >>= 1) {
            sum += __shfl_xor_sync(0xffffffffu, sum, m);
            sq  += __shfl_xor_sync(0xffffffffu, sq,  m);
        }
        float mu  = sum * (1.0f/64.0f);
        float var = sq  * (1.0f/64.0f) - mu*mu;
        float rs  = rsqrtf(var + 1e-5f);
        #pragma unroll
        for (int k = 0; k < 4; k++) {
            int m = g + 16*k;
            xrow[r*64 + m] = (y[k] - mu)*rs*lg_s[m] + lb_s[m];
        }
    }
    __syncthreads();

    // phase 3: xz GEMM. thread owns output column t; W row t in registers.
    {
        const float4* W4 = (const float4*)((img ? w1 : w0) + t*64);
        float w[64];
        #pragma unroll
        for (int q = 0; q < 16; q++) {
            float4 v = __ldg(W4 + q);
            w[4*q]=v.x; w[4*q+1]=v.y; w[4*q+2]=v.z; w[4*q+3]=v.w;
        }
        float* xzout = g_xz + (size_t)img*NROW*256 + ((size_t)(b*CC + c0))*256;
        for (int r4 = 0; r4 < 16; r4 += 4) {
            float a0=0.f, a1=0.f, a2=0.f, a3=0.f;
            #pragma unroll
            for (int q = 0; q < 16; q++) {
                float4 x0 = *(const float4*)&xrow[(r4+0)*64 + q*4];
                float4 x1 = *(const float4*)&xrow[(r4+1)*64 + q*4];
                float4 x2 = *(const float4*)&xrow[(r4+2)*64 + q*4];
                float4 x3 = *(const float4*)&xrow[(r4+3)*64 + q*4];
                a0 = fmaf(x0.x,w[4*q],a0); a0 = fmaf(x0.y,w[4*q+1],a0);
                a0 = fmaf(x0.z,w[4*q+2],a0); a0 = fmaf(x0.w,w[4*q+3],a0);
                a1 = fmaf(x1.x,w[4*q],a1); a1 = fmaf(x1.y,w[4*q+1],a1);
                a1 = fmaf(x1.z,w[4*q+2],a1); a1 = fmaf(x1.w,w[4*q+3],a1);
                a2 = fmaf(x2.x,w[4*q],a2); a2 = fmaf(x2.y,w[4*q+1],a2);
                a2 = fmaf(x2.z,w[4*q+2],a2); a2 = fmaf(x2.w,w[4*q+3],a2);
                a3 = fmaf(x3.x,w[4*q],a3); a3 = fmaf(x3.y,w[4*q+1],a3);
                a3 = fmaf(x3.z,w[4*q+2],a3); a3 = fmaf(x3.w,w[4*q+3],a3);
            }
            xzout[(size_t)(r4+0)*256 + t] = a0;
            xzout[(size_t)(r4+1)*256 + t] = a1;
            xzout[(size_t)(r4+2)*256 + t] = a2;
            xzout[(size_t)(r4+3)*256 + t] = a3;
        }
    }
}

// ============================================================================
// Kernel 3: causal depthwise conv(K=4)+silu, x-proj (128->36), dt-proj+softplus.
// 1152 blocks, 1 tile each; weights staged via coalesced float4 from prepped
// globals. Tail-free GEMM (B/C 32x32 = 256 2x2 tiles; dt split-k).
// ============================================================================
__global__ __launch_bounds__(256) void k_conv_proj(AP P)
{
    int br = blockIdx.z, b = blockIdx.y;
    int p0 = blockIdx.x * 32;
    const BP Bp = P.br[br];

    __shared__ __align__(16) float xs[35*128];
    __shared__ __align__(16) float xp_s[128*36];
    __shared__ float dbc_s[32*36];
    __shared__ __align__(16) float cw_s[512];
    __shared__ __align__(16) float dtw_s[512];
    __shared__ __align__(16) float cb_s[128], dtb_s[128];

    int t = threadIdx.x;
    {   // vectorized weight staging from prepped linear arrays (L2-hot)
        const float4* wsrc = (const float4*)(g_wxp + br*4608);
        #pragma unroll
        for (int i0 = 0; i0 < 1152; i0 += 256) ((float4*)xp_s)[i0 + t] = wsrc[i0 + t];
        if (t < 128)       ((float4*)cw_s )[t]     = ((const float4*)(g_wcv + br*512))[t];
        else               ((float4*)dtw_s)[t-128] = ((const float4*)(g_wdt + br*512))[t-128];
        if (t < 32)        ((float4*)cb_s )[t]     = __ldg((const float4*)Bp.cb  + t);
        else if (t < 64)   ((float4*)dtb_s)[t-32]  = __ldg((const float4*)Bp.dtb + (t-32));
    }

    const float* xzsrc = g_xz + ((br == 2) ? (size_t)NROW*256 : 0);
    for (int i = t; i < 35*128; i += 256) {
        int r = i >> 7, d = i & 127;
        int p = p0 - 3 + r;
        float v = 0.0f;
        if (p >= 0) {
            int l = (br == 1) ? (767 - p) : p;
            v = xzsrc[(size_t)(b*LL + l)*256 + d];
        }
        xs[i] = v;
    }
    __syncthreads();

    // causal depthwise conv + silu
    float xc[16];
    #pragma unroll
    for (int it = 0; it < 16; it++) {
        int i = t + it*256;
        int p = i >> 7, d = i & 127;
        float acc = cb_s[d];
        #pragma unroll
        for (int kk = 0; kk < 4; kk++)
            acc = fmaf(cw_s[kk*128 + d], xs[(p+kk)*128 + d], acc);
        float sg = 1.0f / (1.0f + __expf(-acc));
        xc[it] = acc * sg;
    }
    __syncthreads();
    #pragma unroll
    for (int it = 0; it < 16; it++) {
        int i = t + it*256;
        int p = i >> 7, d = i & 127;
        xs[(p+3)*128 + d] = xc[it];
    }
    __syncthreads();

    // B/C GEMM: 32 rows x 32 cols (j=4..35), 2x2 tiles, all 256 threads
    {
        int pg = t >> 4, jg = t & 15;
        int p = 2*pg, j = 4 + 2*jg;
        float a00=0.f, a01=0.f, a10=0.f, a11=0.f;
        const float* xr0 = xs + (p+3)*128;
        const float* xr1 = xs + (p+4)*128;
        const float* wc  = xp_s + j;
        #pragma unroll 4
        for (int k = 0; k < 128; k += 2) {
            float2 x0 = *(const float2*)&xr0[k];
            float2 x1 = *(const float2*)&xr1[k];
            float2 u0 = *(const float2*)&wc[k*36];
            float2 u1 = *(const float2*)&wc[(k+1)*36];
            a00 = fmaf(x0.x, u0.x, a00); a01 = fmaf(x0.x, u0.y, a01);
            a10 = fmaf(x1.x, u0.x, a10); a11 = fmaf(x1.x, u0.y, a11);
            a00 = fmaf(x0.y, u1.x, a00); a01 = fmaf(x0.y, u1.y, a01);
            a10 = fmaf(x1.y, u1.x, a10); a11 = fmaf(x1.y, u1.y, a11);
        }
        dbc_s[p*36 + j]       = a00;
        dbc_s[p*36 + j + 1]   = a01;
        dbc_s[(p+1)*36 + j]   = a10;
        dbc_s[(p+1)*36 + j+1] = a11;
    }
    // dt columns (j=0..3): 128 outputs, split-k (2 threads each)
    {
        int oi = t >> 1, half = t & 1;
        int p = oi >> 2, j = oi & 3;
        const float* xr = xs + (p+3)*128 + half*64;
        const float* wc = xp_s + (half*64)*36 + j;
        float acc = 0.0f;
        #pragma unroll 8
        for (int k = 0; k < 64; k += 2) {
            float2 x = *(const float2*)&xr[k];
            acc = fmaf(x.x, wc[k*36],     acc);
            acc = fmaf(x.y, wc[(k+1)*36], acc);
        }
        acc += __shfl_xor_sync(0xffffffffu, acc, 1);
        if (half == 0) dbc_s[p*36 + j] = acc;
    }
    __syncthreads();

    // dt = softplus(dbc[:4] @ dtw^T + dtb); write fused (dt, xconv) float2
    size_t obase = (size_t)((br*BB + b)*LL + p0) * DI;
    #pragma unroll
    for (int it = 0; it < 16; it++) {
        int i = t + it*256;
        int p = i >> 7, d = i & 127;
        float acc = dtb_s[d];
        #pragma unroll
        for (int r = 0; r < 4; r++)
            acc = fmaf(dtw_s[r*128 + d], dbc_s[p*36 + r], acc);
        float sp = (acc > 20.0f) ? acc : log1pf(__expf(acc));
        g_dtx[obase + i] = make_float2(sp, xs[(p+3)*128 + d]);
    }
    // B/C permuted: row*32 + q*8 + k
    size_t sbase = (size_t)((br*BB + b)*LL + p0) * 32;
    for (int i = t; i < 1024; i += 256) {
        int p = i >> 5, c = i & 31;
        int q = c >> 3, k = c & 7;
        float v = (k < 4) ? dbc_s[p*36 + 4  + q + 4*k]
                          : dbc_s[p*36 + 20 + q + 4*(k-4)];
        g_bc[sbase + i] = v;
    }
}

// ============================================================================
// Kernel 4a: scan pass 1 — per-chunk (P, q), chunks 0..4.
// grid (4 dg * 5 ch, 16, 3) = 960 blocks, 128 thr = 32 d x 4 q.
// ============================================================================
__global__ __launch_bounds__(128) void k_scan1(AP P)
{
    int bx = blockIdx.x;
    int dg = bx / 5, ch = bx - dg*5;
    int b = blockIdx.y, br = blockIdx.z;
    int d0 = dg * 32;
    int t  = threadIdx.x;
    int dl = t >> 2, q = t & 3;
    int d  = d0 + dl;

    float A[4], h[4] = {0,0,0,0}, Pp[4] = {1,1,1,1};
    #pragma unroll
    for (int k = 0; k < 4; k++) A[k] = __ldg(g_A + br*2048 + d*DS + q + 4*k);

    __shared__ __align__(16) float2 sdtx[STG*32];
    __shared__ __align__(16) float  sb[STG*16];

    int bb = br*BB + b;
    size_t rbase = (size_t)bb * LL;

    for (int sub = 0; sub < 2; sub++) {
        int q0 = ch*CHL + sub*STG;
        __syncthreads();
        for (int i = t; i < STG*32; i += 128) {
            int tt = i >> 5, dd = i & 31;
            sdtx[i] = g_dtx[(rbase + q0 + tt)*DI + d0 + dd];
        }
        for (int i = t; i < STG*16; i += 128) {
            int tt = i >> 4, c = i & 15;
            sb[i] = g_bc[(rbase + q0 + tt)*32 + (c>>2)*8 + (c&3)];
        }
        __syncthreads();

        for (int tb = 0; tb < STG; tb += 4) {
            float2 dx[4]; float4 bq[4];
            #pragma unroll
            for (int j = 0; j < 4; j++) {
                dx[j] = sdtx[(tb+j)*32 + dl];
                bq[j] = *(const float4*)&sb[((tb+j)*4 + q)*4];
            }
            float e[4][4];
            #pragma unroll
            for (int j = 0; j < 4; j++) {
                e[j][0] = __expf(dx[j].x*A[0]);
                e[j][1] = __expf(dx[j].x*A[1]);
                e[j][2] = __expf(dx[j].x*A[2]);
                e[j][3] = __expf(dx[j].x*A[3]);
            }
            #pragma unroll
            for (int j = 0; j < 4; j++) {
                float u = dx[j].x * dx[j].y;
                h[0] = fmaf(e[j][0], h[0], bq[j].x * u);
                h[1] = fmaf(e[j][1], h[1], bq[j].y * u);
                h[2] = fmaf(e[j][2], h[2], bq[j].z * u);
                h[3] = fmaf(e[j][3], h[3], bq[j].w * u);
            }
            #pragma unroll
            for (int k = 0; k < 4; k++)
                Pp[k] *= (e[0][k]*e[1][k])*(e[2][k]*e[3][k]);
        }
    }
    size_t pidx = ((size_t)(bb*5 + ch))*2048 + (size_t)d*16 + q;
    #pragma unroll
    for (int k = 0; k < 4; k++) {
        g_P[pidx + 4*k] = Pp[k];
        g_q[pidx + 4*k] = h[k];
    }
}

// ============================================================================
// Kernel 4b: scan pass 2 — inline boundary combine; per-(row,dg) partial dots
// against v. grid (4 dg * 6 ch, 16, 3) = 1152 blocks, 128 thr.
// ============================================================================
__global__ __launch_bounds__(128) void k_scan2(AP P)
{
    int bx = blockIdx.x;
    int dg = bx / 6, ch = bx - dg*6;
    int b = blockIdx.y, br = blockIdx.z;
    int d0 = dg * 32;
    int t  = threadIdx.x;
    int dl = t >> 2, q = t & 3;
    int d  = d0 + dl;
    const BP Bp = P.br[br];

    float A[4];
    #pragma unroll
    for (int k = 0; k < 4; k++) A[k] = __ldg(g_A + br*2048 + d*DS + q + 4*k);
    float Dp = __ldg(Bp.Dp + d);

    int bb = br*BB + b;
    float h[4] = {0,0,0,0};
    for (int c = 0; c < ch; c++) {
        size_t s = ((size_t)(bb*5 + c))*2048 + (size_t)d*16 + q;
        #pragma unroll
        for (int k = 0; k < 4; k++)
            h[k] = fmaf(g_P[s + 4*k], h[k], g_q[s + 4*k]);
    }

    __shared__ __align__(16) float2 sdtx[STG*32];
    __shared__ __align__(16) float  sbc[STG*32];
    __shared__ float sy[STG*32];
    __shared__ float v_s[32];

    if (t < 32) v_s[t] = g_v[d0 + t];

    size_t rbase = (size_t)bb * LL;
    const float* zsrc = g_xz + ((br == 2) ? (size_t)NROW*256 : 0)
                             + (size_t)b*LL*256 + 128 + d0;
    const int rev  = (br == 1);
    const int lb   = rev ? 767 : 0;
    const int lsgn = rev ? -1 : 1;

    for (int sub = 0; sub < 2; sub++) {
        int q0 = ch*CHL + sub*STG;
        __syncthreads();
        for (int i = t; i < STG*32; i += 128) {
            int tt = i >> 5, dd = i & 31;
            sdtx[i] = g_dtx[(rbase + q0 + tt)*DI + d0 + dd];
            sbc[i]  = g_bc [(rbase + q0 + tt)*32 + dd];
        }
        __syncthreads();

        for (int tb = 0; tb < STG; tb += 4) {
            float2 dx[4]; float4 bq[4], cq[4]; float py[4];
            #pragma unroll
            for (int j = 0; j < 4; j++) {
                dx[j] = sdtx[(tb+j)*32 + dl];
                bq[j] = *(const float4*)&sbc[(tb+j)*32 + q*8];
                cq[j] = *(const float4*)&sbc[(tb+j)*32 + q*8 + 4];
            }
            float e[4][4];
            #pragma unroll
            for (int j = 0; j < 4; j++) {
                e[j][0] = __expf(dx[j].x*A[0]);
                e[j][1] = __expf(dx[j].x*A[1]);
                e[j][2] = __expf(dx[j].x*A[2]);
                e[j][3] = __expf(dx[j].x*A[3]);
            }
            #pragma unroll
            for (int j = 0; j < 4; j++) {
                float u = dx[j].x * dx[j].y;
                h[0] = fmaf(e[j][0], h[0], bq[j].x * u);
                h[1] = fmaf(e[j][1], h[1], bq[j].y * u);
                h[2] = fmaf(e[j][2], h[2], bq[j].z * u);
                h[3] = fmaf(e[j][3], h[3], bq[j].w * u);
                float p = h[0]*cq[j].x;
                p = fmaf(h[1], cq[j].y, p);
                p = fmaf(h[2], cq[j].z, p);
                py[j] = fmaf(h[3], cq[j].w, p);
            }
            #pragma unroll
            for (int j = 0; j < 4; j++) {
                py[j] += __shfl_xor_sync(0xffffffffu, py[j], 2);
                py[j] += __shfl_xor_sync(0xffffffffu, py[j], 1);
            }
            if (q == 0) {
                #pragma unroll
                for (int j = 0; j < 4; j++)
                    sy[(tb+j)*32 + dl] = fmaf(dx[j].y, Dp, py[j]);
            }
        }
        __syncthreads();

        // gated partial dot with v: 2 threads per row, 16 d's each
        {
            int row  = t >> 1, half = t & 1;
            int qq   = q0 + row;
            int l    = lb + lsgn*qq;
            const float* zr = zsrc + (size_t)l*256 + half*16;
            const float* yr = sy + row*32 + half*16;
            const float* vr = v_s + half*16;
            float acc = 0.0f;
            #pragma unroll
            for (int dd = 0; dd < 16; dd++) {
                float zv = zr[dd];
                float sg = zv / (1.0f + __expf(-zv));
                acc = fmaf(yr[dd]*sg, vr[dd], acc);
            }
            acc += __shfl_xor_sync(0xffffffffu, acc, 1);
            if (half == 0)
                g_part[((size_t)(b*LL + l))*12 + br*4 + dg] = acc;
        }
    }
}

// ============================================================================
// Kernel 5: att = sigmoid((sum of 12 partials + post_b)/2) + 1e-6
// ============================================================================
__global__ __launch_bounds__(256) void k_final(
    const float* __restrict__ pb, float* __restrict__ out)
{
    int row = blockIdx.x*256 + threadIdx.x;
    const float4* p = (const float4*)(g_part + (size_t)row*12);
    float4 a = p[0], b4 = p[1], c = p[2];
    float s = (a.x+a.y)+(a.z+a.w) + (b4.x+b4.y)+(b4.z+b4.w) + (c.x+c.y)+(c.z+c.w);
    float o = (s + __ldg(pb)) * 0.5f;
    out[row] = 1.0f / (1.0f + __expf(-o)) + 1e-6f;
}

// ============================================================================
extern "C" void kernel_launch(void* const* d_in, const int* in_sizes, int n_in,
                              void* d_out, int out_size)
{
    const float* img1 = (const float*)d_in[0];
    const float* img2 = (const float*)d_in[1];
    const float* pre_w = (const float*)d_in[2];
    const float* pre_b = (const float*)d_in[3];
    const float* ln_g  = (const float*)d_in[4];
    const float* ln_b  = (const float*)d_in[5];
    const float* in_proj_w   = (const float*)d_in[6];
    const float* in_proj_s_w = (const float*)d_in[7];
    const float* out_proj_w  = (const float*)d_in[8];
    const float* post_w = (const float*)d_in[9];
    const float* post_b = (const float*)d_in[10];

    AP P;
    for (int t = 0; t < 3; t++) {
        int o = 11 + 7*t;              // f, b, s
        P.br[t].cw   = (const float*)d_in[o+0];
        P.br[t].cb   = (const float*)d_in[o+1];
        P.br[t].xp   = (const float*)d_in[o+2];
        P.br[t].dtw  = (const float*)d_in[o+3];
        P.br[t].dtb  = (const float*)d_in[o+4];
        P.br[t].Alog = (const float*)d_in[o+5];
        P.br[t].Dp   = (const float*)d_in[o+6];
    }

    k_prep_w<<<3, 256>>>(P);
    k_prep_A<<<3, 256>>>(P);
    k_prep_v<<<1, 128>>>(out_proj_w, post_w);
    k_front<<<dim3(48, 16, 2), 256>>>(img1, img2, pre_w, pre_b, ln_g, ln_b,
                                      in_proj_w, in_proj_s_w);
    k_conv_proj<<<dim3(24, 16, 3), 256>>>(P);
    k_scan1<<<dim3(20, 16, 3), 128>>>(P);
    k_scan2<<<dim3(24, 16, 3), 128>>>(P);
    k_final<<<48, 256>>>(post_b, (float*)d_out);
    (void)in_sizes; (void)n_in; (void)out_size;
}

// round 9
// speedup vs baseline: 1.2140x; 1.0130x over previous
#include <cuda_runtime.h>
#include <math.h>

// Problem constants
#define BB   16
#define CC   768          // channels == sequence length L
#define LL   768
#define DM   64           // d_model
#define DI   128          // d_inner
#define DS   16           // d_state
#define NROW (BB*CC)      // 12288 rows per image / per branch

#define NCH  6            // scan chunks
#define CHL  128          // chunk length
#define STG  64           // smem staging length (2 subs per chunk)

// ---------------- scratch (device globals; allocation-free rule) ------------
__device__ float  g_xz[2u*NROW*256];     // in_proj outputs, (img, b*L+l, 256)
__device__ float2 g_dtx[3u*NROW*DI];     // (softplus dt, silu(conv x)) per branch, scan order
__device__ float  g_bc[3u*NROW*32];      // B/C permuted: row*32 + q*8 + k:
                                         //   k<4 -> B[q+4k], k>=4 -> C[q+4(k-4)]
__device__ float  g_v[DI];               // out_proj_w^T @ post_w  (collapsed epilogue)
__device__ float  g_part[(size_t)NROW*12]; // per (b,l): 12 partials (3 br x 4 dg)
// chunked-scan intermediates
__device__ float  g_P[48u*5*2048];       // per-chunk state decay products
__device__ float  g_q[48u*5*2048];       // per-chunk local end states
// prepped weights (linear, load-friendly layouts)
__device__ float  g_wxp[3u*4608];        // xproj transposed: [br][k*36+j]
__device__ float  g_wcv[3u*512];         // conv w k-major:   [br][kk*128+d]
__device__ float  g_wdt[3u*512];         // dt w r-major:     [br][r*128+d]
__device__ float  g_A  [3u*2048];        // -exp(A_log):      [br][d*16+s]

struct BP { const float *cw, *cb, *xp, *dtw, *dtb, *Alog, *Dp; };
struct AP { BP br[3]; };

// ============================================================================
// Prep kernels (tiny; also place k_front at ncu's captured 4th launch)
// ============================================================================
__global__ __launch_bounds__(256) void k_prep_w(AP P)
{
    int br = blockIdx.x, t = threadIdx.x;
    const BP Bp = P.br[br];
    float* wxp = g_wxp + br*4608;
    for (int i = t; i < 4608; i += 256) {
        int k = i / 36, j = i - k*36;
        wxp[i] = __ldg(Bp.xp + j*128 + k);         // xproj_w[j][k]
    }
    float* wcv = g_wcv + br*512;
    float* wdt = g_wdt + br*512;
    for (int i = t; i < 512; i += 256) {
        int kk = i >> 7, d = i & 127;
        wcv[i] = __ldg(Bp.cw  + d*4 + kk);
        wdt[i] = __ldg(Bp.dtw + d*4 + kk);
    }
}

__global__ __launch_bounds__(256) void k_prep_A(AP P)
{
    int br = blockIdx.x, t = threadIdx.x;
    const float* al = P.br[br].Alog;
    for (int i = t; i < 2048; i += 256) g_A[br*2048 + i] = -expf(__ldg(al + i));
}

__global__ __launch_bounds__(128) void k_prep_v(
    const float* __restrict__ opw, const float* __restrict__ pw)
{
    int t = threadIdx.x;
    float acc = 0.0f;
    #pragma unroll 8
    for (int m = 0; m < 64; m++) acc = fmaf(__ldg(pw + m), __ldg(opw + m*128 + t), acc);
    g_v[t] = acc;
}

// ============================================================================
// Kernel 1 (fused front): pool 32x32->4x4, pre-proj 16->64, LayerNorm, in_proj
// 64->256. grid (48 c-chunks, 16 b, 2 img), 256 threads.
// Pool phase restructured: fully-coalesced linear float4 loads (one partial
// per load, since each float4 lies inside one pool cell), then a small smem
// reduction. Kills the 72% L1-wavefront bottleneck of the strided version.
// ============================================================================
__global__ __launch_bounds__(256) void k_front(
    const float* __restrict__ img1, const float* __restrict__ img2,
    const float* __restrict__ pre_w, const float* __restrict__ pre_b,
    const float* __restrict__ ln_g,  const float* __restrict__ ln_b,
    const float* __restrict__ w0,    const float* __restrict__ w1)
{
    int img = blockIdx.z, b = blockIdx.y, c0 = blockIdx.x * 16;
    const float* src = (img ? img2 : img1) + ((size_t)(b*CC + c0)) * 1024;

    // part_s padded layout: addr(c, t) = c*296 + (t>>6)*72 + (t&63)
    __shared__ float part_s[16*296];
    __shared__ float pw_s[16*64];        // transposed: pw_s[q*64+m]
    __shared__ float pb_s[64], lg_s[64], lb_s[64];
    __shared__ float pool_s[16*16];
    __shared__ __align__(16) float xrow[16*64];

    int t = threadIdx.x;
    // stage pre weights
    for (int i = t; i < 1024; i += 256) {
        int q = i >> 6, m = i & 63;
        pw_s[i] = __ldg(pre_w + m*16 + q);
    }
    if (t < 64) { pb_s[t] = __ldg(pre_b+t); lg_s[t] = __ldg(ln_g+t); lb_s[t] = __ldg(ln_b+t); }

    // phase 1a: coalesced loads; thread t covers position t of every channel i.
    // float4 f = i*256 + t: channel i, h = t>>3, w4 = t&7 -> inside one cell.
    {
        const float4* s4 = (const float4*)src;
        int toff = (t >> 6)*72 + (t & 63);
        #pragma unroll
        for (int i = 0; i < 16; i++) {
            float4 a = __ldg(s4 + i*256 + t);
            part_s[i*296 + toff] = (a.x + a.y) + (a.z + a.w);
        }
    }
    __syncthreads();

    // phase 1b: reduce 16 contributors per (channel, cell).
    // contributors of (c, pi, pj): addr = c*296 + pi*72 + 8k + 2pj + m
    {
        int c = t >> 4, cell = t & 15;
        int pi = cell >> 2, pj = cell & 3;
        const float* base = part_s + c*296 + pi*72 + 2*pj;
        float s = 0.0f;
        #pragma unroll
        for (int k = 0; k < 8; k++) s += base[8*k] + base[8*k + 1];
        pool_s[c*16 + cell] = s * (1.0f/64.0f);
    }
    __syncthreads();

    // phase 2: pre-proj + LN. 16 threads/row, thread g owns m = g+16k (k=0..3)
    {
        int r = t >> 4, g = t & 15;
        float y[4], sum = 0.0f, sq = 0.0f;
        #pragma unroll
        for (int k = 0; k < 4; k++) {
            int m = g + 16*k;
            float acc = pb_s[m];
            #pragma unroll
            for (int q = 0; q < 16; q++)
                acc = fmaf(pw_s[q*64 + m], pool_s[r*16 + q], acc);
            y[k] = acc; sum += acc; sq = fmaf(acc, acc, sq);
        }
        #pragma unroll
        for (int m = 8; m >= 1; m >>= 1) {
            sum += __shfl_xor_sync(0xffffffffu, sum, m);
            sq  += __shfl_xor_sync(0xffffffffu, sq,  m);
        }
        float mu  = sum * (1.0f/64.0f);
        float var = sq  * (1.0f/64.0f) - mu*mu;
        float rs  = rsqrtf(var + 1e-5f);
        #pragma unroll
        for (int k = 0; k < 4; k++) {
            int m = g + 16*k;
            xrow[r*64 + m] = (y[k] - mu)*rs*lg_s[m] + lb_s[m];
        }
    }
    __syncthreads();

    // phase 3: xz GEMM. thread owns output column t; W row t in registers.
    {
        const float4* W4 = (const float4*)((img ? w1 : w0) + t*64);
        float w[64];
        #pragma unroll
        for (int q = 0; q < 16; q++) {
            float4 v = __ldg(W4 + q);
            w[4*q]=v.x; w[4*q+1]=v.y; w[4*q+2]=v.z; w[4*q+3]=v.w;
        }
        float* xzout = g_xz + (size_t)img*NROW*256 + ((size_t)(b*CC + c0))*256;
        for (int r4 = 0; r4 < 16; r4 += 4) {
            float a0=0.f, a1=0.f, a2=0.f, a3=0.f;
            #pragma unroll
            for (int q = 0; q < 16; q++) {
                float4 x0 = *(const float4*)&xrow[(r4+0)*64 + q*4];
                float4 x1 = *(const float4*)&xrow[(r4+1)*64 + q*4];
                float4 x2 = *(const float4*)&xrow[(r4+2)*64 + q*4];
                float4 x3 = *(const float4*)&xrow[(r4+3)*64 + q*4];
                a0 = fmaf(x0.x,w[4*q],a0); a0 = fmaf(x0.y,w[4*q+1],a0);
                a0 = fmaf(x0.z,w[4*q+2],a0); a0 = fmaf(x0.w,w[4*q+3],a0);
                a1 = fmaf(x1.x,w[4*q],a1); a1 = fmaf(x1.y,w[4*q+1],a1);
                a1 = fmaf(x1.z,w[4*q+2],a1); a1 = fmaf(x1.w,w[4*q+3],a1);
                a2 = fmaf(x2.x,w[4*q],a2); a2 = fmaf(x2.y,w[4*q+1],a2);
                a2 = fmaf(x2.z,w[4*q+2],a2); a2 = fmaf(x2.w,w[4*q+3],a2);
                a3 = fmaf(x3.x,w[4*q],a3); a3 = fmaf(x3.y,w[4*q+1],a3);
                a3 = fmaf(x3.z,w[4*q+2],a3); a3 = fmaf(x3.w,w[4*q+3],a3);
            }
            xzout[(size_t)(r4+0)*256 + t] = a0;
            xzout[(size_t)(r4+1)*256 + t] = a1;
            xzout[(size_t)(r4+2)*256 + t] = a2;
            xzout[(size_t)(r4+3)*256 + t] = a3;
        }
    }
}

// ============================================================================
// Kernel 3: causal depthwise conv(K=4)+silu, x-proj (128->36), dt-proj+softplus.
// ============================================================================
__global__ __launch_bounds__(256) void k_conv_proj(AP P)
{
    int br = blockIdx.z, b = blockIdx.y;
    int p0 = blockIdx.x * 32;
    const BP Bp = P.br[br];

    __shared__ __align__(16) float xs[35*128];
    __shared__ __align__(16) float xp_s[128*36];
    __shared__ float dbc_s[32*36];
    __shared__ __align__(16) float cw_s[512];
    __shared__ __align__(16) float dtw_s[512];
    __shared__ __align__(16) float cb_s[128], dtb_s[128];

    int t = threadIdx.x;
    {   // vectorized weight staging from prepped linear arrays (L2-hot)
        const float4* wsrc = (const float4*)(g_wxp + br*4608);
        #pragma unroll
        for (int i0 = 0; i0 < 1152; i0 += 256) ((float4*)xp_s)[i0 + t] = wsrc[i0 + t];
        if (t < 128)       ((float4*)cw_s )[t]     = ((const float4*)(g_wcv + br*512))[t];
        else               ((float4*)dtw_s)[t-128] = ((const float4*)(g_wdt + br*512))[t-128];
        if (t < 32)        ((float4*)cb_s )[t]     = __ldg((const float4*)Bp.cb  + t);
        else if (t < 64)   ((float4*)dtb_s)[t-32]  = __ldg((const float4*)Bp.dtb + (t-32));
    }

    const float* xzsrc = g_xz + ((br == 2) ? (size_t)NROW*256 : 0);
    for (int i = t; i < 35*128; i += 256) {
        int r = i >> 7, d = i & 127;
        int p = p0 - 3 + r;
        float v = 0.0f;
        if (p >= 0) {
            int l = (br == 1) ? (767 - p) : p;
            v = xzsrc[(size_t)(b*LL + l)*256 + d];
        }
        xs[i] = v;
    }
    __syncthreads();

    // causal depthwise conv + silu
    float xc[16];
    #pragma unroll
    for (int it = 0; it < 16; it++) {
        int i = t + it*256;
        int p = i >> 7, d = i & 127;
        float acc = cb_s[d];
        #pragma unroll
        for (int kk = 0; kk < 4; kk++)
            acc = fmaf(cw_s[kk*128 + d], xs[(p+kk)*128 + d], acc);
        float sg = 1.0f / (1.0f + __expf(-acc));
        xc[it] = acc * sg;
    }
    __syncthreads();
    #pragma unroll
    for (int it = 0; it < 16; it++) {
        int i = t + it*256;
        int p = i >> 7, d = i & 127;
        xs[(p+3)*128 + d] = xc[it];
    }
    __syncthreads();

    // B/C GEMM: 32 rows x 32 cols (j=4..35), 2x2 tiles, all 256 threads
    {
        int pg = t >> 4, jg = t & 15;
        int p = 2*pg, j = 4 + 2*jg;
        float a00=0.f, a01=0.f, a10=0.f, a11=0.f;
        const float* xr0 = xs + (p+3)*128;
        const float* xr1 = xs + (p+4)*128;
        const float* wc  = xp_s + j;
        #pragma unroll 4
        for (int k = 0; k < 128; k += 2) {
            float2 x0 = *(const float2*)&xr0[k];
            float2 x1 = *(const float2*)&xr1[k];
            float2 u0 = *(const float2*)&wc[k*36];
            float2 u1 = *(const float2*)&wc[(k+1)*36];
            a00 = fmaf(x0.x, u0.x, a00); a01 = fmaf(x0.x, u0.y, a01);
            a10 = fmaf(x1.x, u0.x, a10); a11 = fmaf(x1.x, u0.y, a11);
            a00 = fmaf(x0.y, u1.x, a00); a01 = fmaf(x0.y, u1.y, a01);
            a10 = fmaf(x1.y, u1.x, a10); a11 = fmaf(x1.y, u1.y, a11);
        }
        dbc_s[p*36 + j]       = a00;
        dbc_s[p*36 + j + 1]   = a01;
        dbc_s[(p+1)*36 + j]   = a10;
        dbc_s[(p+1)*36 + j+1] = a11;
    }
    // dt columns (j=0..3): 128 outputs, split-k (2 threads each)
    {
        int oi = t >> 1, half = t & 1;
        int p = oi >> 2, j = oi & 3;
        const float* xr = xs + (p+3)*128 + half*64;
        const float* wc = xp_s + (half*64)*36 + j;
        float acc = 0.0f;
        #pragma unroll 8
        for (int k = 0; k < 64; k += 2) {
            float2 x = *(const float2*)&xr[k];
            acc = fmaf(x.x, wc[k*36],     acc);
            acc = fmaf(x.y, wc[(k+1)*36], acc);
        }
        acc += __shfl_xor_sync(0xffffffffu, acc, 1);
        if (half == 0) dbc_s[p*36 + j] = acc;
    }
    __syncthreads();

    // dt = softplus(dbc[:4] @ dtw^T + dtb); write fused (dt, xconv) float2
    size_t obase = (size_t)((br*BB + b)*LL + p0) * DI;
    #pragma unroll
    for (int it = 0; it < 16; it++) {
        int i = t + it*256;
        int p = i >> 7, d = i & 127;
        float acc = dtb_s[d];
        #pragma unroll
        for (int r = 0; r < 4; r++)
            acc = fmaf(dtw_s[r*128 + d], dbc_s[p*36 + r], acc);
        float sp = (acc > 20.0f) ? acc : log1pf(__expf(acc));
        g_dtx[obase + i] = make_float2(sp, xs[(p+3)*128 + d]);
    }
    // B/C permuted: row*32 + q*8 + k
    size_t sbase = (size_t)((br*BB + b)*LL + p0) * 32;
    for (int i = t; i < 1024; i += 256) {
        int p = i >> 5, c = i & 31;
        int q = c >> 3, k = c & 7;
        float v = (k < 4) ? dbc_s[p*36 + 4  + q + 4*k]
                          : dbc_s[p*36 + 20 + q + 4*(k-4)];
        g_bc[sbase + i] = v;
    }
}

// ============================================================================
// Kernel 4a: scan pass 1 — per-chunk (P, q), chunks 0..4.
// grid (4 dg * 5 ch, 16, 3) = 960 blocks, 128 thr = 32 d x 4 q.
// ============================================================================
__global__ __launch_bounds__(128) void k_scan1(AP P)
{
    int bx = blockIdx.x;
    int dg = bx / 5, ch = bx - dg*5;
    int b = blockIdx.y, br = blockIdx.z;
    int d0 = dg * 32;
    int t  = threadIdx.x;
    int dl = t >> 2, q = t & 3;
    int d  = d0 + dl;

    float A[4], h[4] = {0,0,0,0}, Pp[4] = {1,1,1,1};
    #pragma unroll
    for (int k = 0; k < 4; k++) A[k] = __ldg(g_A + br*2048 + d*DS + q + 4*k);

    __shared__ __align__(16) float2 sdtx[STG*32];
    __shared__ __align__(16) float  sb[STG*16];

    int bb = br*BB + b;
    size_t rbase = (size_t)bb * LL;

    for (int sub = 0; sub < 2; sub++) {
        int q0 = ch*CHL + sub*STG;
        __syncthreads();
        for (int i = t; i < STG*32; i += 128) {
            int tt = i >> 5, dd = i & 31;
            sdtx[i] = g_dtx[(rbase + q0 + tt)*DI + d0 + dd];
        }
        for (int i = t; i < STG*16; i += 128) {
            int tt = i >> 4, c = i & 15;
            sb[i] = g_bc[(rbase + q0 + tt)*32 + (c>>2)*8 + (c&3)];
        }
        __syncthreads();

        for (int tb = 0; tb < STG; tb += 4) {
            float2 dx[4]; float4 bq[4];
            #pragma unroll
            for (int j = 0; j < 4; j++) {
                dx[j] = sdtx[(tb+j)*32 + dl];
                bq[j] = *(const float4*)&sb[((tb+j)*4 + q)*4];
            }
            float e[4][4];
            #pragma unroll
            for (int j = 0; j < 4; j++) {
                e[j][0] = __expf(dx[j].x*A[0]);
                e[j][1] = __expf(dx[j].x*A[1]);
                e[j][2] = __expf(dx[j].x*A[2]);
                e[j][3] = __expf(dx[j].x*A[3]);
            }
            #pragma unroll
            for (int j = 0; j < 4; j++) {
                float u = dx[j].x * dx[j].y;
                h[0] = fmaf(e[j][0], h[0], bq[j].x * u);
                h[1] = fmaf(e[j][1], h[1], bq[j].y * u);
                h[2] = fmaf(e[j][2], h[2], bq[j].z * u);
                h[3] = fmaf(e[j][3], h[3], bq[j].w * u);
            }
            #pragma unroll
            for (int k = 0; k < 4; k++)
                Pp[k] *= (e[0][k]*e[1][k])*(e[2][k]*e[3][k]);
        }
    }
    size_t pidx = ((size_t)(bb*5 + ch))*2048 + (size_t)d*16 + q;
    #pragma unroll
    for (int k = 0; k < 4; k++) {
        g_P[pidx + 4*k] = Pp[k];
        g_q[pidx + 4*k] = h[k];
    }
}

// ============================================================================
// Kernel 4b: scan pass 2 — inline boundary combine; per-(row,dg) partial dots
// against v. grid (4 dg * 6 ch, 16, 3) = 1152 blocks, 128 thr.
// ============================================================================
__global__ __launch_bounds__(128) void k_scan2(AP P)
{
    int bx = blockIdx.x;
    int dg = bx / 6, ch = bx - dg*6;
    int b = blockIdx.y, br = blockIdx.z;
    int d0 = dg * 32;
    int t  = threadIdx.x;
    int dl = t >> 2, q = t & 3;
    int d  = d0 + dl;
    const BP Bp = P.br[br];

    float A[4];
    #pragma unroll
    for (int k = 0; k < 4; k++) A[k] = __ldg(g_A + br*2048 + d*DS + q + 4*k);
    float Dp = __ldg(Bp.Dp + d);

    int bb = br*BB + b;
    float h[4] = {0,0,0,0};
    for (int c = 0; c < ch; c++) {
        size_t s = ((size_t)(bb*5 + c))*2048 + (size_t)d*16 + q;
        #pragma unroll
        for (int k = 0; k < 4; k++)
            h[k] = fmaf(g_P[s + 4*k], h[k], g_q[s + 4*k]);
    }

    __shared__ __align__(16) float2 sdtx[STG*32];
    __shared__ __align__(16) float  sbc[STG*32];
    __shared__ float sy[STG*32];
    __shared__ float v_s[32];

    if (t < 32) v_s[t] = g_v[d0 + t];

    size_t rbase = (size_t)bb * LL;
    const float* zsrc = g_xz + ((br == 2) ? (size_t)NROW*256 : 0)
                             + (size_t)b*LL*256 + 128 + d0;
    const int rev  = (br == 1);
    const int lb   = rev ? 767 : 0;
    const int lsgn = rev ? -1 : 1;

    for (int sub = 0; sub < 2; sub++) {
        int q0 = ch*CHL + sub*STG;
        __syncthreads();
        for (int i = t; i < STG*32; i += 128) {
            int tt = i >> 5, dd = i & 31;
            sdtx[i] = g_dtx[(rbase + q0 + tt)*DI + d0 + dd];
            sbc[i]  = g_bc [(rbase + q0 + tt)*32 + dd];
        }
        __syncthreads();

        for (int tb = 0; tb < STG; tb += 4) {
            float2 dx[4]; float4 bq[4], cq[4]; float py[4];
            #pragma unroll
            for (int j = 0; j < 4; j++) {
                dx[j] = sdtx[(tb+j)*32 + dl];
                bq[j] = *(const float4*)&sbc[(tb+j)*32 + q*8];
                cq[j] = *(const float4*)&sbc[(tb+j)*32 + q*8 + 4];
            }
            float e[4][4];
            #pragma unroll
            for (int j = 0; j < 4; j++) {
                e[j][0] = __expf(dx[j].x*A[0]);
                e[j][1] = __expf(dx[j].x*A[1]);
                e[j][2] = __expf(dx[j].x*A[2]);
                e[j][3] = __expf(dx[j].x*A[3]);
            }
            #pragma unroll
            for (int j = 0; j < 4; j++) {
                float u = dx[j].x * dx[j].y;
                h[0] = fmaf(e[j][0], h[0], bq[j].x * u);
                h[1] = fmaf(e[j][1], h[1], bq[j].y * u);
                h[2] = fmaf(e[j][2], h[2], bq[j].z * u);
                h[3] = fmaf(e[j][3], h[3], bq[j].w * u);
                float p = h[0]*cq[j].x;
                p = fmaf(h[1], cq[j].y, p);
                p = fmaf(h[2], cq[j].z, p);
                py[j] = fmaf(h[3], cq[j].w, p);
            }
            #pragma unroll
            for (int j = 0; j < 4; j++) {
                py[j] += __shfl_xor_sync(0xffffffffu, py[j], 2);
                py[j] += __shfl_xor_sync(0xffffffffu, py[j], 1);
            }
            if (q == 0) {
                #pragma unroll
                for (int j = 0; j < 4; j++)
                    sy[(tb+j)*32 + dl] = fmaf(dx[j].y, Dp, py[j]);
            }
        }
        __syncthreads();

        // gated partial dot with v: 2 threads per row, 16 d's each
        {
            int row  = t >> 1, half = t & 1;
            int qq   = q0 + row;
            int l    = lb + lsgn*qq;
            const float* zr = zsrc + (size_t)l*256 + half*16;
            const float* yr = sy + row*32 + half*16;
            const float* vr = v_s + half*16;
            float acc = 0.0f;
            #pragma unroll
            for (int dd = 0; dd < 16; dd++) {
                float zv = zr[dd];
                float sg = zv / (1.0f + __expf(-zv));
                acc = fmaf(yr[dd]*sg, vr[dd], acc);
            }
            acc += __shfl_xor_sync(0xffffffffu, acc, 1);
            if (half == 0)
                g_part[((size_t)(b*LL + l))*12 + br*4 + dg] = acc;
        }
    }
}

// ============================================================================
// Kernel 5: att = sigmoid((sum of 12 partials + post_b)/2) + 1e-6
// ============================================================================
__global__ __launch_bounds__(256) void k_final(
    const float* __restrict__ pb, float* __restrict__ out)
{
    int row = blockIdx.x*256 + threadIdx.x;
    const float4* p = (const float4*)(g_part + (size_t)row*12);
    float4 a = p[0], b4 = p[1], c = p[2];
    float s = (a.x+a.y)+(a.z+a.w) + (b4.x+b4.y)+(b4.z+b4.w) + (c.x+c.y)+(c.z+c.w);
    float o = (s + __ldg(pb)) * 0.5f;
    out[row] = 1.0f / (1.0f + __expf(-o)) + 1e-6f;
}

// ============================================================================
extern "C" void kernel_launch(void* const* d_in, const int* in_sizes, int n_in,
                              void* d_out, int out_size)
{
    const float* img1 = (const float*)d_in[0];
    const float* img2 = (const float*)d_in[1];
    const float* pre_w = (const float*)d_in[2];
    const float* pre_b = (const float*)d_in[3];
    const float* ln_g  = (const float*)d_in[4];
    const float* ln_b  = (const float*)d_in[5];
    const float* in_proj_w   = (const float*)d_in[6];
    const float* in_proj_s_w = (const float*)d_in[7];
    const float* out_proj_w  = (const float*)d_in[8];
    const float* post_w = (const float*)d_in[9];
    const float* post_b = (const float*)d_in[10];

    AP P;
    for (int t = 0; t < 3; t++) {
        int o = 11 + 7*t;              // f, b, s
        P.br[t].cw   = (const float*)d_in[o+0];
        P.br[t].cb   = (const float*)d_in[o+1];
        P.br[t].xp   = (const float*)d_in[o+2];
        P.br[t].dtw  = (const float*)d_in[o+3];
        P.br[t].dtb  = (const float*)d_in[o+4];
        P.br[t].Alog = (const float*)d_in[o+5];
        P.br[t].Dp   = (const float*)d_in[o+6];
    }

    k_prep_w<<<3, 256>>>(P);
    k_prep_A<<<3, 256>>>(P);
    k_prep_v<<<1, 128>>>(out_proj_w, post_w);
    k_front<<<dim3(48, 16, 2), 256>>>(img1, img2, pre_w, pre_b, ln_g, ln_b,
                                      in_proj_w, in_proj_s_w);
    k_conv_proj<<<dim3(24, 16, 3), 256>>>(P);
    k_scan1<<<dim3(20, 16, 3), 128>>>(P);
    k_scan2<<<dim3(24, 16, 3), 128>>>(P);
    k_final<<<48, 256>>>(post_b, (float*)d_out);
    (void)in_sizes; (void)n_in; (void)out_size;
}